// round 8
// baseline (speedup 1.0000x reference)
#include <cuda_runtime.h>
#include <cstdint>

#define DIMC    512
#define NHEADS  8
#define HD      64
#define BATCH   8
#define NTOK    1024     // 32*32
#define NKTOK   256      // 16*16
#define MKV     2048     // NKTOK * NHEADS
#define KCONV   2048     // 512 * 2 * 2

// ---------------- scratch (device globals; no allocation allowed) ------------
__device__ float g_q[BATCH * NTOK * DIMC];      // (b, n, c)  16 MB
__device__ float g_w2[KCONV * DIMC];            // conv weight as GEMM B, 4 MB
__device__ float g_xkv[BATCH * NKTOK * DIMC];   // conv out / LN in-place, 4 MB
__device__ float g_k[BATCH * NKTOK * DIMC];     // == (b, m, 64) view, 4 MB
__device__ float g_v[BATCH * NKTOK * DIMC];     // 4 MB
__device__ float g_ao[BATCH * NTOK * DIMC];     // attention out (b, n, c), 16 MB

// ---------------- tf32 helpers ----------------------------------------------
__device__ __forceinline__ uint32_t cvt_tf32(float f) {
    uint32_t r; asm("cvt.rna.tf32.f32 %0, %1;" : "=r"(r) : "f"(f)); return r;
}
__device__ __forceinline__ float cvt_tf32f(float f) {
    return __uint_as_float(cvt_tf32(f));
}
__device__ __forceinline__ void mma_tf32(float* d, const uint32_t* a,
                                         uint32_t b0, uint32_t b1) {
    asm volatile(
        "mma.sync.aligned.m16n8k8.row.col.f32.tf32.tf32.f32 "
        "{%0,%1,%2,%3}, {%4,%5,%6,%7}, {%8,%9}, {%0,%1,%2,%3};"
        : "+f"(d[0]), "+f"(d[1]), "+f"(d[2]), "+f"(d[3])
        : "r"(a[0]), "r"(a[1]), "r"(a[2]), "r"(a[3]), "r"(b0), "r"(b1));
}

// ---------------- packed f32x2 helpers (exact fp32, 2 FMA / issue slot) ------
#define PACK2(out, lo, hi) \
    asm("mov.b64 %0, {%1, %2};" : "=l"(out) : "f"(lo), "f"(hi))
#define UNPACK2(lo, hi, in) \
    asm("mov.b64 {%0, %1}, %2;" : "=f"(lo), "=f"(hi) : "l"(in))
#define FMA2(d, a, b) \
    asm("fma.rn.f32x2 %0, %1, %2, %3;" : "=l"(d) : "l"(a), "l"(b), "l"(d))

// ---------------- sr_w transpose: (co,ci,kh,kw) -> W2[(khw*512+ci)][co] ------
__global__ __launch_bounds__(256) void prep_w2_kernel(
    const float* __restrict__ srw, float* __restrict__ w2)
{
    int idx = blockIdx.x * 256 + threadIdx.x;     // over KCONV*DIMC
    if (idx >= KCONV * DIMC) return;
    int co  = idx & 511;
    int r   = idx >> 9;          // khw*512 + ci
    int dhw = r >> 9;
    int ci  = r & 511;
    w2[idx] = srw[((co * 512 + ci) << 2) + dhw];
}

// ---------------- fp32 GEMM via FFMA2, 128x64 tile, BK=16, 8x4/thread -------
// Accumulators packed as row-pairs: accp[i2][j] = (C[2*i2][j], C[2*i2+1][j]).
// A row-pairs come free from aligned float4 LDS; B cols are broadcast-packed.
// MODE 0: C = A(MxK) @ B(KxN) + bias
// MODE 1: A gathered from x for the SR conv (K = 2048 = 4 chunks of 512)
// MODE 2: split epilogue: col<512 -> C (k), col>=512 -> C2 (v)
template<int MODE>
__global__ __launch_bounds__(256) void sgemm_kernel(
    const float* __restrict__ A, const float* __restrict__ Bm,
    const float* __restrict__ bias, float* __restrict__ C,
    float* __restrict__ C2, int M, int N, int K)
{
    constexpr int BM = 128, BN = 64, BK = 16, TM = 8, TN = 4;
    __shared__ float As[BK][BM + 4];   // transposed: As[k][m]
    __shared__ float Bs[BK][BN + 4];   // Bs[k][n]

    const int tid = threadIdx.x;
    const int tx  = tid & 15;          // 16 col groups
    const int ty  = tid >> 4;          // 16 row groups
    const int row0 = blockIdx.y * BM;
    const int col0 = blockIdx.x * BN;

    const int a_r = tid >> 2;          // 0..63
    const int a_c = (tid & 3) << 2;    // 0,4,8,12
    const int b_r = tid >> 4;          // 0..15
    const int b_c = (tid & 15) << 2;

    unsigned long long accp[TM/2][TN];   // row-pair x col, packed f32x2
    #pragma unroll
    for (int i = 0; i < TM/2; ++i)
        #pragma unroll
        for (int j = 0; j < TN; ++j) accp[i][j] = 0ull;

    for (int k0 = 0; k0 < K; k0 += BK) {
        // ---- load A tile (2 rows per thread) ----
        #pragma unroll
        for (int it = 0; it < 2; ++it) {
            int r = a_r + it * 64;
            int grow = row0 + r;
            float4 av;
            if (MODE == 1) {
                int bb = grow >> 8;
                int t  = grow & 255;
                int oi = t >> 4, oj = t & 15;
                int kk = k0 + a_c;
                int chunk = kk >> 9;            // which of 4 taps
                int ci = kk & 511;
                int n  = ((oi << 1) + (chunk >> 1)) * 32 + (oj << 1) + (chunk & 1);
                av = *(const float4*)(A + ((size_t)(bb * 1024 + n) * 512 + ci));
            } else {
                av = *(const float4*)(A + (size_t)grow * K + k0 + a_c);
            }
            As[a_c + 0][r] = av.x;
            As[a_c + 1][r] = av.y;
            As[a_c + 2][r] = av.z;
            As[a_c + 3][r] = av.w;
        }
        // ---- load B tile ----
        {
            float4 bv = *(const float4*)(Bm + (size_t)(k0 + b_r) * N + col0 + b_c);
            *(float4*)&Bs[b_r][b_c] = bv;
        }
        __syncthreads();

        #pragma unroll
        for (int kk = 0; kk < BK; ++kk) {
            float4 a1 = *(const float4*)&As[kk][ty * TM];
            float4 a2 = *(const float4*)&As[kk][ty * TM + 4];
            float4 b4 = *(const float4*)&Bs[kk][tx * TN];
            unsigned long long pa[TM/2];
            PACK2(pa[0], a1.x, a1.y);
            PACK2(pa[1], a1.z, a1.w);
            PACK2(pa[2], a2.x, a2.y);
            PACK2(pa[3], a2.z, a2.w);
            unsigned long long pb[TN];
            PACK2(pb[0], b4.x, b4.x);
            PACK2(pb[1], b4.y, b4.y);
            PACK2(pb[2], b4.z, b4.z);
            PACK2(pb[3], b4.w, b4.w);
            #pragma unroll
            for (int i = 0; i < TM/2; ++i)
                #pragma unroll
                for (int j = 0; j < TN; ++j)
                    FMA2(accp[i][j], pa[i], pb[j]);
        }
        __syncthreads();
    }

    // ---- epilogue: unpack then store ----
    float acc[TM][TN];
    #pragma unroll
    for (int i = 0; i < TM/2; ++i)
        #pragma unroll
        for (int j = 0; j < TN; ++j)
            UNPACK2(acc[2*i][j], acc[2*i+1][j], accp[i][j]);

    #pragma unroll
    for (int i = 0; i < TM; ++i) {
        int r = row0 + ty * TM + i;
        #pragma unroll
        for (int j = 0; j < TN; ++j) {
            int c = col0 + tx * TN + j;
            float v = acc[i][j] + bias[c];
            if (MODE == 2) {
                if (c < 512) C [(size_t)r * 512 + c]       = v;
                else         C2[(size_t)r * 512 + (c-512)] = v;
            } else {
                C[(size_t)r * N + c] = v;
            }
        }
    }
}

// ---------------- LayerNorm over last dim (512), in place --------------------
__global__ __launch_bounds__(128) void ln_kernel(
    float* __restrict__ x, const float* __restrict__ g, const float* __restrict__ bt)
{
    __shared__ float sA[4], sB[4];
    int row = blockIdx.x;
    float* p = x + (size_t)row * 512;
    int c = threadIdx.x * 4;
    float4 v = *(const float4*)(p + c);
    float s  = v.x + v.y + v.z + v.w;
    float s2 = v.x*v.x + v.y*v.y + v.z*v.z + v.w*v.w;
    #pragma unroll
    for (int o = 16; o; o >>= 1) {
        s  += __shfl_xor_sync(0xffffffffu, s,  o);
        s2 += __shfl_xor_sync(0xffffffffu, s2, o);
    }
    int w = threadIdx.x >> 5;
    if ((threadIdx.x & 31) == 0) { sA[w] = s; sB[w] = s2; }
    __syncthreads();
    s  = sA[0] + sA[1] + sA[2] + sA[3];
    s2 = sB[0] + sB[1] + sB[2] + sB[3];
    float mu  = s * (1.f / 512.f);
    float var = s2 * (1.f / 512.f) - mu * mu;
    float inv = rsqrtf(var + 1e-5f);
    float4 gv = *(const float4*)(g + c);
    float4 bv = *(const float4*)(bt + c);
    float4 ov;
    ov.x = (v.x - mu) * inv * gv.x + bv.x;
    ov.y = (v.y - mu) * inv * gv.y + bv.y;
    ov.z = (v.z - mu) * inv * gv.z + bv.z;
    ov.w = (v.w - mu) * inv * gv.w + bv.w;
    *(float4*)(p + c) = ov;
}

// ---------------- TF32 tensor-core flash attention ---------------------------
// grid (16 qtiles, 8 heads, 8 batch), 128 threads = 4 warps.
__global__ __launch_bounds__(128) void attn_tc_kernel(
    const float* __restrict__ q, const float* __restrict__ kmat,
    const float* __restrict__ vmat, float* __restrict__ out)
{
    constexpr int PK = 68, PVV = 72, PP = 68;   // pitches: conflict-free per access pattern
    extern __shared__ float sm[];
    float* Ks = sm;                  // [key][d]   64 x PK
    float* Vs = Ks + 64 * PK;        // [key][d]   64 x PVV
    float* Ps = Vs + 64 * PVV;       // [qrow][key] 64 x PP (per-warp slices)

    const int tid  = threadIdx.x;
    const int w    = tid >> 5;
    const int lane = tid & 31;
    const int g    = lane >> 2;      // 0..7
    const int tig  = lane & 3;       // 0..3
    const int qt = blockIdx.x, h = blockIdx.y, b = blockIdx.z;

    // ---- load Q fragments (rows w*16 + g + {0,8}; cols 8s + tig + {0,4}) ----
    uint32_t qa[8][4];
    {
        const float* qb = q + ((size_t)(b * 1024 + qt * 64 + w * 16) * 512 + h * 64);
        #pragma unroll
        for (int s = 0; s < 8; ++s) {
            qa[s][0] = cvt_tf32(qb[(size_t)(g    ) * 512 + 8*s + tig    ] * 0.125f);
            qa[s][1] = cvt_tf32(qb[(size_t)(g + 8) * 512 + 8*s + tig    ] * 0.125f);
            qa[s][2] = cvt_tf32(qb[(size_t)(g    ) * 512 + 8*s + tig + 4] * 0.125f);
            qa[s][3] = cvt_tf32(qb[(size_t)(g + 8) * 512 + 8*s + tig + 4] * 0.125f);
        }
    }

    float o[8][4];
    #pragma unroll
    for (int j = 0; j < 8; ++j)
        #pragma unroll
        for (int i = 0; i < 4; ++i) o[j][i] = 0.f;

    float m0 = -1e30f, m1 = -1e30f, l0 = 0.f, l1 = 0.f;

    const float* kbase = kmat + (size_t)b * 2048 * 64;
    const float* vbase = vmat + (size_t)b * 2048 * 64;

    for (int kt = 0; kt < 32; ++kt) {
        __syncthreads();   // all warps done with previous Ks/Vs
        // ---- cooperative load + tf32-convert of K,V tiles ----
        {
            const float* kg = kbase + kt * 64 * 64;
            const float* vg = vbase + kt * 64 * 64;
            #pragma unroll
            for (int rep = 0; rep < 8; ++rep) {
                int idx = rep * 512 + tid * 4;
                int r = idx >> 6, c = idx & 63;
                float4 kf = *(const float4*)(kg + idx);
                Ks[r * PK + c + 0] = cvt_tf32f(kf.x);
                Ks[r * PK + c + 1] = cvt_tf32f(kf.y);
                Ks[r * PK + c + 2] = cvt_tf32f(kf.z);
                Ks[r * PK + c + 3] = cvt_tf32f(kf.w);
                float4 vf = *(const float4*)(vg + idx);
                Vs[r * PVV + c + 0] = cvt_tf32f(vf.x);
                Vs[r * PVV + c + 1] = cvt_tf32f(vf.y);
                Vs[r * PVV + c + 2] = cvt_tf32f(vf.z);
                Vs[r * PVV + c + 3] = cvt_tf32f(vf.w);
            }
        }
        __syncthreads();

        // ---- S = (Q*scale) @ K^T : 8 n-tiles x 8 k-steps, j-inner for ILP ----
        float sfr[8][4];
        #pragma unroll
        for (int j = 0; j < 8; ++j)
            #pragma unroll
            for (int i = 0; i < 4; ++i) sfr[j][i] = 0.f;

        #pragma unroll
        for (int s = 0; s < 8; ++s) {
            #pragma unroll
            for (int j = 0; j < 8; ++j) {
                const float* kr = Ks + (8*j + g) * PK + 8*s + tig;
                uint32_t b0 = __float_as_uint(kr[0]);
                uint32_t b1 = __float_as_uint(kr[4]);
                mma_tf32(sfr[j], qa[s], b0, b1);
            }
        }

        // ---- online softmax (rows g and g+8 of this warp's 16-row tile) ----
        float mx0 = -1e30f, mx1 = -1e30f;
        #pragma unroll
        for (int j = 0; j < 8; ++j) {
            mx0 = fmaxf(mx0, fmaxf(sfr[j][0], sfr[j][1]));
            mx1 = fmaxf(mx1, fmaxf(sfr[j][2], sfr[j][3]));
        }
        mx0 = fmaxf(mx0, __shfl_xor_sync(0xffffffffu, mx0, 1));
        mx0 = fmaxf(mx0, __shfl_xor_sync(0xffffffffu, mx0, 2));
        mx1 = fmaxf(mx1, __shfl_xor_sync(0xffffffffu, mx1, 1));
        mx1 = fmaxf(mx1, __shfl_xor_sync(0xffffffffu, mx1, 2));
        float mn0 = fmaxf(m0, mx0), mn1 = fmaxf(m1, mx1);
        float al0 = __expf(m0 - mn0), al1 = __expf(m1 - mn1);
        float s0 = 0.f, s1 = 0.f;
        #pragma unroll
        for (int j = 0; j < 8; ++j) {
            sfr[j][0] = __expf(sfr[j][0] - mn0); s0 += sfr[j][0];
            sfr[j][1] = __expf(sfr[j][1] - mn0); s0 += sfr[j][1];
            sfr[j][2] = __expf(sfr[j][2] - mn1); s1 += sfr[j][2];
            sfr[j][3] = __expf(sfr[j][3] - mn1); s1 += sfr[j][3];
        }
        s0 += __shfl_xor_sync(0xffffffffu, s0, 1);
        s0 += __shfl_xor_sync(0xffffffffu, s0, 2);
        s1 += __shfl_xor_sync(0xffffffffu, s1, 1);
        s1 += __shfl_xor_sync(0xffffffffu, s1, 2);
        l0 = l0 * al0 + s0;
        l1 = l1 * al1 + s1;
        m0 = mn0; m1 = mn1;
        #pragma unroll
        for (int j = 0; j < 8; ++j) {
            o[j][0] *= al0; o[j][1] *= al0;
            o[j][2] *= al1; o[j][3] *= al1;
        }

        // ---- P c-frags -> smem (warp-private rows), reload as a-frags ----
        {
            float* p0 = Ps + (w * 16 + g) * PP;
            float* p1 = Ps + (w * 16 + g + 8) * PP;
            #pragma unroll
            for (int j = 0; j < 8; ++j) {
                p0[8*j + 2*tig    ] = cvt_tf32f(sfr[j][0]);
                p0[8*j + 2*tig + 1] = cvt_tf32f(sfr[j][1]);
                p1[8*j + 2*tig    ] = cvt_tf32f(sfr[j][2]);
                p1[8*j + 2*tig + 1] = cvt_tf32f(sfr[j][3]);
            }
        }
        __syncwarp();

        uint32_t pa[8][4];
        {
            const float* pr0 = Ps + (w * 16 + g) * PP;
            const float* pr1 = Ps + (w * 16 + g + 8) * PP;
            #pragma unroll
            for (int s = 0; s < 8; ++s) {
                pa[s][0] = __float_as_uint(pr0[8*s + tig    ]);
                pa[s][1] = __float_as_uint(pr1[8*s + tig    ]);
                pa[s][2] = __float_as_uint(pr0[8*s + tig + 4]);
                pa[s][3] = __float_as_uint(pr1[8*s + tig + 4]);
            }
        }

        // ---- O += P @ V : j-inner, 8 independent accumulator chains ----
        #pragma unroll
        for (int s = 0; s < 8; ++s) {
            #pragma unroll
            for (int j = 0; j < 8; ++j) {
                uint32_t b0 = __float_as_uint(Vs[(8*s + tig    ) * PVV + 8*j + g]);
                uint32_t b1 = __float_as_uint(Vs[(8*s + tig + 4) * PVV + 8*j + g]);
                mma_tf32(o[j], pa[s], b0, b1);
            }
        }
    }

    // ---- finalize ----
    float li0 = 1.f / l0, li1 = 1.f / l1;
    float* ob = out + ((size_t)(b * 1024 + qt * 64 + w * 16) * 512 + h * 64);
    #pragma unroll
    for (int j = 0; j < 8; ++j) {
        ob[(size_t)(g    ) * 512 + 8*j + 2*tig    ] = o[j][0] * li0;
        ob[(size_t)(g    ) * 512 + 8*j + 2*tig + 1] = o[j][1] * li0;
        ob[(size_t)(g + 8) * 512 + 8*j + 2*tig    ] = o[j][2] * li1;
        ob[(size_t)(g + 8) * 512 + 8*j + 2*tig + 1] = o[j][3] * li1;
    }
}

// -----------------------------------------------------------------------------
extern "C" void kernel_launch(void* const* d_in, const int* in_sizes, int n_in,
                              void* d_out, int out_size)
{
    const float* x      = (const float*)d_in[0];
    const float* q_w    = (const float*)d_in[3];
    const float* q_b    = (const float*)d_in[4];
    const float* kv_w   = (const float*)d_in[5];
    const float* kv_b   = (const float*)d_in[6];
    const float* sr_w   = (const float*)d_in[7];
    const float* sr_b   = (const float*)d_in[8];
    const float* ln_g   = (const float*)d_in[9];
    const float* ln_b   = (const float*)d_in[10];
    const float* proj_w = (const float*)d_in[11];
    const float* proj_b = (const float*)d_in[12];
    float* out = (float*)d_out;

    float *gq, *gw2, *gxkv, *gk, *gv, *gao;
    cudaGetSymbolAddress((void**)&gq,   g_q);
    cudaGetSymbolAddress((void**)&gw2,  g_w2);
    cudaGetSymbolAddress((void**)&gxkv, g_xkv);
    cudaGetSymbolAddress((void**)&gk,   g_k);
    cudaGetSymbolAddress((void**)&gv,   g_v);
    cudaGetSymbolAddress((void**)&gao,  g_ao);

    // 1) conv weight -> GEMM layout
    prep_w2_kernel<<<(KCONV * DIMC + 255) / 256, 256>>>(sr_w, gw2);

    // 2) q projection: (8192x512) @ (512x512)
    sgemm_kernel<0><<<dim3(512/64, 8192/128), 256>>>(
        x, q_w, q_b, gq, nullptr, 8192, 512, 512);

    // 3) SR conv as gathered GEMM: (2048x2048) @ (2048x512)
    sgemm_kernel<1><<<dim3(512/64, 2048/128), 256>>>(
        x, gw2, sr_b, gxkv, nullptr, 2048, 512, KCONV);

    // 4) LayerNorm
    ln_kernel<<<BATCH * NKTOK, 128>>>(gxkv, ln_g, ln_b);

    // 5) kv projection with k/v split: (2048x512) @ (512x1024)
    sgemm_kernel<2><<<dim3(1024/64, 2048/128), 256>>>(
        gxkv, kv_w, kv_b, gk, gv, 2048, 1024, 512);

    // 6) tensor-core flash attention
    {
        const int smem_bytes = (64 * (68 + 72 + 68)) * sizeof(float);  // 53248
        cudaFuncSetAttribute(attn_tc_kernel,
                             cudaFuncAttributeMaxDynamicSharedMemorySize, smem_bytes);
        attn_tc_kernel<<<dim3(16, NHEADS, BATCH), 128, smem_bytes>>>(gq, gk, gv, gao);
    }

    // 7) output projection -> d_out
    sgemm_kernel<0><<<dim3(512/64, 8192/128), 256>>>(
        gao, proj_w, proj_b, out, nullptr, 8192, 512, 512);
}

// round 15
// speedup vs baseline: 1.8365x; 1.8365x over previous
#include <cuda_runtime.h>
#include <cstdint>

#define DIMC    512
#define NHEADS  8
#define HD      64
#define BATCH   8
#define NTOK    1024     // 32*32
#define NKTOK   256      // 16*16
#define MKV     2048     // NKTOK * NHEADS
#define KCONV   2048     // 512 * 2 * 2

// ---------------- scratch (device globals; no allocation allowed) ------------
__device__ float g_q[BATCH * NTOK * DIMC];      // (b, n, c)  16 MB
__device__ float g_w2[KCONV * DIMC];            // conv weight as GEMM B, 4 MB
__device__ float g_xkv[BATCH * NKTOK * DIMC];   // conv out / LN in-place, 4 MB
__device__ float g_k[BATCH * NKTOK * DIMC];     // == (b, m, 64) view, 4 MB
__device__ float g_v[BATCH * NKTOK * DIMC];     // 4 MB
__device__ float g_ao[BATCH * NTOK * DIMC];     // attention out (b, n, c), 16 MB

// ---------------- tf32 helpers ----------------------------------------------
__device__ __forceinline__ uint32_t cvt_tf32(float f) {
    uint32_t r; asm("cvt.rna.tf32.f32 %0, %1;" : "=r"(r) : "f"(f)); return r;
}
__device__ __forceinline__ float cvt_tf32f(float f) {
    return __uint_as_float(cvt_tf32(f));
}
__device__ __forceinline__ void mma_tf32(float* d, const uint32_t* a,
                                         uint32_t b0, uint32_t b1) {
    asm volatile(
        "mma.sync.aligned.m16n8k8.row.col.f32.tf32.tf32.f32 "
        "{%0,%1,%2,%3}, {%4,%5,%6,%7}, {%8,%9}, {%0,%1,%2,%3};"
        : "+f"(d[0]), "+f"(d[1]), "+f"(d[2]), "+f"(d[3])
        : "r"(a[0]), "r"(a[1]), "r"(a[2]), "r"(a[3]), "r"(b0), "r"(b1));
}

// ---------------- sr_w transpose: (co,ci,kh,kw) -> W2[(khw*512+ci)][co] ------
__global__ __launch_bounds__(256) void prep_w2_kernel(
    const float* __restrict__ srw, float* __restrict__ w2)
{
    int idx = blockIdx.x * 256 + threadIdx.x;     // over KCONV*DIMC
    if (idx >= KCONV * DIMC) return;
    int co  = idx & 511;
    int r   = idx >> 9;          // khw*512 + ci
    int dhw = r >> 9;
    int ci  = r & 511;
    w2[idx] = srw[((co * 512 + ci) << 2) + dhw];
}

// ---------------- TF32 tensor-core GEMM, 128x64 tile, BK=32, 8 warps --------
// Warp w owns output rows [row0 + w*16, +16) x all 64 cols (8 n-tiles).
// Fragment maps identical to the HW-validated attention kernel:
//   a-frag: A[g / g+8][8s+tig / +4]   from As[k][m] (transposed smem)
//   b-frag: B_op[n][k] = W[k][n]      from Bs[k][n]
//   c-frag: rows g/g+8, cols 2tig/2tig+1 within each 8-wide n-tile
// MODE 0: C = A(MxK) @ B(KxN) + bias
// MODE 1: A gathered from x for the SR conv (K = 2048 = 4 chunks of 512)
// MODE 2: split epilogue: col<512 -> C (k), col>=512 -> C2 (v)
template<int MODE>
__global__ __launch_bounds__(256) void tgemm_kernel(
    const float* __restrict__ A, const float* __restrict__ Bm,
    const float* __restrict__ bias, float* __restrict__ C,
    float* __restrict__ C2, int M, int N, int K)
{
    constexpr int BM = 128, BN = 64, BK = 32;
    constexpr int PA = 132, PB = 68;
    __shared__ float As[BK][PA];     // As[k][m], tf32 values
    __shared__ float Bs[BK][PB];     // Bs[k][n], tf32 values

    const int tid  = threadIdx.x;
    const int w    = tid >> 5;       // 0..7
    const int lane = tid & 31;
    const int g    = lane >> 2;      // 0..7
    const int tig  = lane & 3;       // 0..3
    const int row0 = blockIdx.y * BM;
    const int col0 = blockIdx.x * BN;

    // A loader: thread covers row a_r, 16 cols at half*16
    const int a_r    = tid >> 1;          // 0..127
    const int a_half = (tid & 1) << 4;    // 0 or 16
    // B loader: thread covers row b_r, 8 cols at b_c
    const int b_r = tid >> 3;             // 0..31
    const int b_c = (tid & 7) << 3;       // 0..56

    float acc[8][4];
    #pragma unroll
    for (int j = 0; j < 8; ++j)
        #pragma unroll
        for (int i = 0; i < 4; ++i) acc[j][i] = 0.f;

    for (int k0 = 0; k0 < K; k0 += BK) {
        // ---- load + convert A tile (128 x 32) ----
        #pragma unroll
        for (int q = 0; q < 4; ++q) {
            int cc = a_half + q * 4;
            int grow = row0 + a_r;
            float4 av;
            if (MODE == 1) {
                // gathered conv row: grow = b*256 + t, t = oi*16+oj
                int bb = grow >> 8;
                int t  = grow & 255;
                int oi = t >> 4, oj = t & 15;
                int kk = k0 + cc;
                int chunk = kk >> 9;           // conv tap (uniform across float4)
                int ci = kk & 511;
                int n  = ((oi << 1) + (chunk >> 1)) * 32 + (oj << 1) + (chunk & 1);
                av = *(const float4*)(A + ((size_t)(bb * 1024 + n) * 512 + ci));
            } else {
                av = *(const float4*)(A + (size_t)grow * K + k0 + cc);
            }
            As[cc + 0][a_r] = cvt_tf32f(av.x);
            As[cc + 1][a_r] = cvt_tf32f(av.y);
            As[cc + 2][a_r] = cvt_tf32f(av.z);
            As[cc + 3][a_r] = cvt_tf32f(av.w);
        }
        // ---- load + convert B tile (32 x 64) ----
        #pragma unroll
        for (int q = 0; q < 2; ++q) {
            float4 bv = *(const float4*)(Bm + (size_t)(k0 + b_r) * N + col0 + b_c + q * 4);
            float4 cv;
            cv.x = cvt_tf32f(bv.x); cv.y = cvt_tf32f(bv.y);
            cv.z = cvt_tf32f(bv.z); cv.w = cvt_tf32f(bv.w);
            *(float4*)&Bs[b_r][b_c + q * 4] = cv;
        }
        __syncthreads();

        // ---- 4 k-steps x 8 n-tiles of m16n8k8 ----
        #pragma unroll
        for (int s = 0; s < 4; ++s) {
            const int ka = 8 * s + tig;
            uint32_t af[4];
            af[0] = __float_as_uint(As[ka    ][w * 16 + g    ]);
            af[1] = __float_as_uint(As[ka    ][w * 16 + g + 8]);
            af[2] = __float_as_uint(As[ka + 4][w * 16 + g    ]);
            af[3] = __float_as_uint(As[ka + 4][w * 16 + g + 8]);
            #pragma unroll
            for (int j = 0; j < 8; ++j) {
                uint32_t b0 = __float_as_uint(Bs[ka    ][8 * j + g]);
                uint32_t b1 = __float_as_uint(Bs[ka + 4][8 * j + g]);
                mma_tf32(acc[j], af, b0, b1);
            }
        }
        __syncthreads();
    }

    // ---- epilogue: bias + store (float2 per c-frag row) ----
    const int r0 = row0 + w * 16 + g;
    const int r1 = r0 + 8;
    #pragma unroll
    for (int j = 0; j < 8; ++j) {
        int c = col0 + 8 * j + 2 * tig;
        float bx = bias[c], by = bias[c + 1];
        float2 lo = make_float2(acc[j][0] + bx, acc[j][1] + by);
        float2 hi = make_float2(acc[j][2] + bx, acc[j][3] + by);
        if (MODE == 2) {
            if (c < 512) {
                *(float2*)(C  + (size_t)r0 * 512 + c) = lo;
                *(float2*)(C  + (size_t)r1 * 512 + c) = hi;
            } else {
                *(float2*)(C2 + (size_t)r0 * 512 + (c - 512)) = lo;
                *(float2*)(C2 + (size_t)r1 * 512 + (c - 512)) = hi;
            }
        } else {
            *(float2*)(C + (size_t)r0 * N + c) = lo;
            *(float2*)(C + (size_t)r1 * N + c) = hi;
        }
    }
}

// ---------------- LayerNorm over last dim (512), in place --------------------
__global__ __launch_bounds__(128) void ln_kernel(
    float* __restrict__ x, const float* __restrict__ g, const float* __restrict__ bt)
{
    __shared__ float sA[4], sB[4];
    int row = blockIdx.x;
    float* p = x + (size_t)row * 512;
    int c = threadIdx.x * 4;
    float4 v = *(const float4*)(p + c);
    float s  = v.x + v.y + v.z + v.w;
    float s2 = v.x*v.x + v.y*v.y + v.z*v.z + v.w*v.w;
    #pragma unroll
    for (int o = 16; o; o >>= 1) {
        s  += __shfl_xor_sync(0xffffffffu, s,  o);
        s2 += __shfl_xor_sync(0xffffffffu, s2, o);
    }
    int w = threadIdx.x >> 5;
    if ((threadIdx.x & 31) == 0) { sA[w] = s; sB[w] = s2; }
    __syncthreads();
    s  = sA[0] + sA[1] + sA[2] + sA[3];
    s2 = sB[0] + sB[1] + sB[2] + sB[3];
    float mu  = s * (1.f / 512.f);
    float var = s2 * (1.f / 512.f) - mu * mu;
    float inv = rsqrtf(var + 1e-5f);
    float4 gv = *(const float4*)(g + c);
    float4 bv = *(const float4*)(bt + c);
    float4 ov;
    ov.x = (v.x - mu) * inv * gv.x + bv.x;
    ov.y = (v.y - mu) * inv * gv.y + bv.y;
    ov.z = (v.z - mu) * inv * gv.z + bv.z;
    ov.w = (v.w - mu) * inv * gv.w + bv.w;
    *(float4*)(p + c) = ov;
}

// ---------------- TF32 tensor-core flash attention ---------------------------
// grid (16 qtiles, 8 heads, 8 batch), 128 threads = 4 warps.
__global__ __launch_bounds__(128) void attn_tc_kernel(
    const float* __restrict__ q, const float* __restrict__ kmat,
    const float* __restrict__ vmat, float* __restrict__ out)
{
    constexpr int PK = 68, PVV = 72, PP = 68;   // pitches: conflict-free per access pattern
    extern __shared__ float sm[];
    float* Ks = sm;                  // [key][d]   64 x PK
    float* Vs = Ks + 64 * PK;        // [key][d]   64 x PVV
    float* Ps = Vs + 64 * PVV;       // [qrow][key] 64 x PP (per-warp slices)

    const int tid  = threadIdx.x;
    const int w    = tid >> 5;
    const int lane = tid & 31;
    const int g    = lane >> 2;      // 0..7
    const int tig  = lane & 3;       // 0..3
    const int qt = blockIdx.x, h = blockIdx.y, b = blockIdx.z;

    // ---- load Q fragments (rows w*16 + g + {0,8}; cols 8s + tig + {0,4}) ----
    uint32_t qa[8][4];
    {
        const float* qb = q + ((size_t)(b * 1024 + qt * 64 + w * 16) * 512 + h * 64);
        #pragma unroll
        for (int s = 0; s < 8; ++s) {
            qa[s][0] = cvt_tf32(qb[(size_t)(g    ) * 512 + 8*s + tig    ] * 0.125f);
            qa[s][1] = cvt_tf32(qb[(size_t)(g + 8) * 512 + 8*s + tig    ] * 0.125f);
            qa[s][2] = cvt_tf32(qb[(size_t)(g    ) * 512 + 8*s + tig + 4] * 0.125f);
            qa[s][3] = cvt_tf32(qb[(size_t)(g + 8) * 512 + 8*s + tig + 4] * 0.125f);
        }
    }

    float o[8][4];
    #pragma unroll
    for (int j = 0; j < 8; ++j)
        #pragma unroll
        for (int i = 0; i < 4; ++i) o[j][i] = 0.f;

    float m0 = -1e30f, m1 = -1e30f, l0 = 0.f, l1 = 0.f;

    const float* kbase = kmat + (size_t)b * 2048 * 64;
    const float* vbase = vmat + (size_t)b * 2048 * 64;

    for (int kt = 0; kt < 32; ++kt) {
        __syncthreads();   // all warps done with previous Ks/Vs
        // ---- cooperative load + tf32-convert of K,V tiles ----
        {
            const float* kg = kbase + kt * 64 * 64;
            const float* vg = vbase + kt * 64 * 64;
            #pragma unroll
            for (int rep = 0; rep < 8; ++rep) {
                int idx = rep * 512 + tid * 4;
                int r = idx >> 6, c = idx & 63;
                float4 kf = *(const float4*)(kg + idx);
                Ks[r * PK + c + 0] = cvt_tf32f(kf.x);
                Ks[r * PK + c + 1] = cvt_tf32f(kf.y);
                Ks[r * PK + c + 2] = cvt_tf32f(kf.z);
                Ks[r * PK + c + 3] = cvt_tf32f(kf.w);
                float4 vf = *(const float4*)(vg + idx);
                Vs[r * PVV + c + 0] = cvt_tf32f(vf.x);
                Vs[r * PVV + c + 1] = cvt_tf32f(vf.y);
                Vs[r * PVV + c + 2] = cvt_tf32f(vf.z);
                Vs[r * PVV + c + 3] = cvt_tf32f(vf.w);
            }
        }
        __syncthreads();

        // ---- S = (Q*scale) @ K^T : 8 n-tiles x 8 k-steps, j-inner for ILP ----
        float sfr[8][4];
        #pragma unroll
        for (int j = 0; j < 8; ++j)
            #pragma unroll
            for (int i = 0; i < 4; ++i) sfr[j][i] = 0.f;

        #pragma unroll
        for (int s = 0; s < 8; ++s) {
            #pragma unroll
            for (int j = 0; j < 8; ++j) {
                const float* kr = Ks + (8*j + g) * PK + 8*s + tig;
                uint32_t b0 = __float_as_uint(kr[0]);
                uint32_t b1 = __float_as_uint(kr[4]);
                mma_tf32(sfr[j], qa[s], b0, b1);
            }
        }

        // ---- online softmax (rows g and g+8 of this warp's 16-row tile) ----
        float mx0 = -1e30f, mx1 = -1e30f;
        #pragma unroll
        for (int j = 0; j < 8; ++j) {
            mx0 = fmaxf(mx0, fmaxf(sfr[j][0], sfr[j][1]));
            mx1 = fmaxf(mx1, fmaxf(sfr[j][2], sfr[j][3]));
        }
        mx0 = fmaxf(mx0, __shfl_xor_sync(0xffffffffu, mx0, 1));
        mx0 = fmaxf(mx0, __shfl_xor_sync(0xffffffffu, mx0, 2));
        mx1 = fmaxf(mx1, __shfl_xor_sync(0xffffffffu, mx1, 1));
        mx1 = fmaxf(mx1, __shfl_xor_sync(0xffffffffu, mx1, 2));
        float mn0 = fmaxf(m0, mx0), mn1 = fmaxf(m1, mx1);
        float al0 = __expf(m0 - mn0), al1 = __expf(m1 - mn1);
        float s0 = 0.f, s1 = 0.f;
        #pragma unroll
        for (int j = 0; j < 8; ++j) {
            sfr[j][0] = __expf(sfr[j][0] - mn0); s0 += sfr[j][0];
            sfr[j][1] = __expf(sfr[j][1] - mn0); s0 += sfr[j][1];
            sfr[j][2] = __expf(sfr[j][2] - mn1); s1 += sfr[j][2];
            sfr[j][3] = __expf(sfr[j][3] - mn1); s1 += sfr[j][3];
        }
        s0 += __shfl_xor_sync(0xffffffffu, s0, 1);
        s0 += __shfl_xor_sync(0xffffffffu, s0, 2);
        s1 += __shfl_xor_sync(0xffffffffu, s1, 1);
        s1 += __shfl_xor_sync(0xffffffffu, s1, 2);
        l0 = l0 * al0 + s0;
        l1 = l1 * al1 + s1;
        m0 = mn0; m1 = mn1;
        #pragma unroll
        for (int j = 0; j < 8; ++j) {
            o[j][0] *= al0; o[j][1] *= al0;
            o[j][2] *= al1; o[j][3] *= al1;
        }

        // ---- P c-frags -> smem (warp-private rows), reload as a-frags ----
        {
            float* p0 = Ps + (w * 16 + g) * PP;
            float* p1 = Ps + (w * 16 + g + 8) * PP;
            #pragma unroll
            for (int j = 0; j < 8; ++j) {
                p0[8*j + 2*tig    ] = cvt_tf32f(sfr[j][0]);
                p0[8*j + 2*tig + 1] = cvt_tf32f(sfr[j][1]);
                p1[8*j + 2*tig    ] = cvt_tf32f(sfr[j][2]);
                p1[8*j + 2*tig + 1] = cvt_tf32f(sfr[j][3]);
            }
        }
        __syncwarp();

        uint32_t pa[8][4];
        {
            const float* pr0 = Ps + (w * 16 + g) * PP;
            const float* pr1 = Ps + (w * 16 + g + 8) * PP;
            #pragma unroll
            for (int s = 0; s < 8; ++s) {
                pa[s][0] = __float_as_uint(pr0[8*s + tig    ]);
                pa[s][1] = __float_as_uint(pr1[8*s + tig    ]);
                pa[s][2] = __float_as_uint(pr0[8*s + tig + 4]);
                pa[s][3] = __float_as_uint(pr1[8*s + tig + 4]);
            }
        }

        // ---- O += P @ V : j-inner, 8 independent accumulator chains ----
        #pragma unroll
        for (int s = 0; s < 8; ++s) {
            #pragma unroll
            for (int j = 0; j < 8; ++j) {
                uint32_t b0 = __float_as_uint(Vs[(8*s + tig    ) * PVV + 8*j + g]);
                uint32_t b1 = __float_as_uint(Vs[(8*s + tig + 4) * PVV + 8*j + g]);
                mma_tf32(o[j], pa[s], b0, b1);
            }
        }
    }

    // ---- finalize ----
    float li0 = 1.f / l0, li1 = 1.f / l1;
    float* ob = out + ((size_t)(b * 1024 + qt * 64 + w * 16) * 512 + h * 64);
    #pragma unroll
    for (int j = 0; j < 8; ++j) {
        ob[(size_t)(g    ) * 512 + 8*j + 2*tig    ] = o[j][0] * li0;
        ob[(size_t)(g    ) * 512 + 8*j + 2*tig + 1] = o[j][1] * li0;
        ob[(size_t)(g + 8) * 512 + 8*j + 2*tig    ] = o[j][2] * li1;
        ob[(size_t)(g + 8) * 512 + 8*j + 2*tig + 1] = o[j][3] * li1;
    }
}

// -----------------------------------------------------------------------------
extern "C" void kernel_launch(void* const* d_in, const int* in_sizes, int n_in,
                              void* d_out, int out_size)
{
    const float* x      = (const float*)d_in[0];
    const float* q_w    = (const float*)d_in[3];
    const float* q_b    = (const float*)d_in[4];
    const float* kv_w   = (const float*)d_in[5];
    const float* kv_b   = (const float*)d_in[6];
    const float* sr_w   = (const float*)d_in[7];
    const float* sr_b   = (const float*)d_in[8];
    const float* ln_g   = (const float*)d_in[9];
    const float* ln_b   = (const float*)d_in[10];
    const float* proj_w = (const float*)d_in[11];
    const float* proj_b = (const float*)d_in[12];
    float* out = (float*)d_out;

    float *gq, *gw2, *gxkv, *gk, *gv, *gao;
    cudaGetSymbolAddress((void**)&gq,   g_q);
    cudaGetSymbolAddress((void**)&gw2,  g_w2);
    cudaGetSymbolAddress((void**)&gxkv, g_xkv);
    cudaGetSymbolAddress((void**)&gk,   g_k);
    cudaGetSymbolAddress((void**)&gv,   g_v);
    cudaGetSymbolAddress((void**)&gao,  g_ao);

    // 1) conv weight -> GEMM layout
    prep_w2_kernel<<<(KCONV * DIMC + 255) / 256, 256>>>(sr_w, gw2);

    // 2) q projection: (8192x512) @ (512x512)
    tgemm_kernel<0><<<dim3(512/64, 8192/128), 256>>>(
        x, q_w, q_b, gq, nullptr, 8192, 512, 512);

    // 3) SR conv as gathered GEMM: (2048x2048) @ (2048x512)
    tgemm_kernel<1><<<dim3(512/64, 2048/128), 256>>>(
        x, gw2, sr_b, gxkv, nullptr, 2048, 512, KCONV);

    // 4) LayerNorm
    ln_kernel<<<BATCH * NKTOK, 128>>>(gxkv, ln_g, ln_b);

    // 5) kv projection with k/v split: (2048x512) @ (512x1024)
    tgemm_kernel<2><<<dim3(1024/64, 2048/128), 256>>>(
        gxkv, kv_w, kv_b, gk, gv, 2048, 1024, 512);

    // 6) tensor-core flash attention
    {
        const int smem_bytes = (64 * (68 + 72 + 68)) * sizeof(float);  // 53248
        cudaFuncSetAttribute(attn_tc_kernel,
                             cudaFuncAttributeMaxDynamicSharedMemorySize, smem_bytes);
        attn_tc_kernel<<<dim3(16, NHEADS, BATCH), 128, smem_bytes>>>(gq, gk, gv, gao);
    }

    // 7) output projection -> d_out
    tgemm_kernel<0><<<dim3(512/64, 8192/128), 256>>>(
        gao, proj_w, proj_b, out, nullptr, 8192, 512, 512);
}